// round 6
// baseline (speedup 1.0000x reference)
#include <cuda_runtime.h>

#define BB   32      // batch (M)
#define TT   512     // time steps
#define HH   1024    // hidden / input dim
#define DD   4       // depth
#define NBLK 148     // persistent blocks (<= SM count, all co-resident)
#define NTHR 256     // 8 warps

// Scratch (device globals: no allocation allowed)
__device__ float g_hb[2][DD][HH][BB];          // double-buffered hidden state, [buf][d][k][m]
__device__ float g_xT[TT][HH][BB];             // transposed input, [t][k][m] (64 MB)
__device__ unsigned long long g_bar = 0;       // monotonic grid barrier counter (replay-safe)

// ---------------------------------------------------------------------------
// Grid barrier: monotonic counter. Every replay adds exact multiples of
// gridDim.x per barrier, so no reset is ever needed (graph-replay safe).
// ---------------------------------------------------------------------------
__device__ __forceinline__ void gridbar() {
    __syncthreads();
    if (threadIdx.x == 0) {
        __threadfence();  // release: publish this block's writes
        unsigned long long my = atomicAdd(&g_bar, 1ULL);
        unsigned long long target =
            (my / (unsigned long long)gridDim.x + 1ULL) * (unsigned long long)gridDim.x;
        unsigned long long cur;
        do {
            asm volatile("ld.acquire.gpu.u64 %0, [%1];" : "=l"(cur) : "l"(&g_bar));
        } while (cur < target);
    }
    __syncthreads();
}

// ---------------------------------------------------------------------------
// Per-warp dot segment: acc[c] += sum_k A[k][lane] * W[k][c], k in [k0,k1)
// A is [K][32] (lane-coalesced), W rows are H-wide; W already offset by col0.
// ---------------------------------------------------------------------------
template<int CT>
__device__ __forceinline__ void dotseg(const float* __restrict__ A,
                                       const float* __restrict__ W,
                                       int k0, int k1, int lane, float* acc) {
    const float* Ap = A + k0 * BB + lane;
    const float* Wp = W + k0 * HH;
#pragma unroll 4
    for (int k = k0; k < k1; ++k) {
        float a = __ldg(Ap);
        float4 w0 = __ldg((const float4*)Wp);
        acc[0] += a * w0.x; acc[1] += a * w0.y;
        acc[2] += a * w0.z; acc[3] += a * w0.w;
        if (CT == 8) {
            float4 w1 = __ldg(((const float4*)Wp) + 1);
            acc[4] += a * w1.x; acc[5] += a * w1.y;
            acc[6] += a * w1.z; acc[7] += a * w1.w;
        }
        Ap += BB; Wp += HH;
    }
}

// ---------------------------------------------------------------------------
// One (t,d) stage for a GEMM block: CT columns x 32 rows, full K in-block.
//   pre = A1 @ Wx[:,cols] + h_d(t-1) @ Wh_d[256g:, cols] + b
//   h   = tanh(pre)  -> hb_new[d], out
// ---------------------------------------------------------------------------
template<int CT>
__device__ __forceinline__ void do_stage(int t, int d,
                                         const float* __restrict__ Wx,
                                         const float* __restrict__ Whd,
                                         const float* __restrict__ bias,
                                         float* __restrict__ out,
                                         const float* __restrict__ hb_old_d,
                                         const float* __restrict__ A1,
                                         float* __restrict__ hb_new_d,
                                         float (*red)[256]) {
    const int tid  = threadIdx.x;
    const int lane = tid & 31;
    const int wid  = tid >> 5;
    const int col0 = blockIdx.x * CT;
    const int grp  = col0 >> 8;          // period group of this column tile

    float acc[CT];
#pragma unroll
    for (int c = 0; c < CT; ++c) acc[c] = 0.f;

    // Part 1: feed-forward input (x_t or h_{d-1}(t)), full K=1024, warp k-slice 128
    dotseg<CT>(A1, Wx + col0, wid * 128, wid * 128 + 128, lane, acc);

    // Part 2: recurrent, masked rows [256g, 1024)
    const int base = grp << 8;
    const int sl   = (HH - base) >> 3;   // 128/96/64/32 per warp
    dotseg<CT>(hb_old_d, Whd + col0, base + wid * sl, base + wid * sl + sl, lane, acc);

    // Cross-warp reduction in SMEM
#pragma unroll
    for (int c = 0; c < CT; ++c) red[wid][c * 32 + lane] = acc[c];
    __syncthreads();

    if (tid < CT * 32) {
        float s = 0.f;
#pragma unroll
        for (int w = 0; w < 8; ++w) s += red[w][tid];
        const int c = tid >> 5, m = tid & 31;
        const int col = col0 + c;
        const float h = tanhf(s + __ldg(bias + col));
        hb_new_d[col * BB + m] = h;
        out[((m * TT + (t - 1)) * DD + d) * HH + col] = h;
    }
}

// ---------------------------------------------------------------------------
// Main persistent kernel
// ---------------------------------------------------------------------------
__global__ void __launch_bounds__(NTHR, 1)
cwrnn_kernel(const float* __restrict__ Wx0,
             const float* __restrict__ Wxd,
             const float* __restrict__ Wh,
             const float* __restrict__ bias,
             float* __restrict__ out) {
    __shared__ float red[8][256];
    const int tid = threadIdx.x;

    // Zero both hidden-state buffers (fresh state every run / graph replay)
    {
        float* hz = &g_hb[0][0][0][0];
        for (int i = blockIdx.x * NTHR + tid; i < 2 * DD * HH * BB; i += NBLK * NTHR)
            hz[i] = 0.f;
    }
    gridbar();

    for (int t = 1; t <= TT; ++t) {
        // v = min(ctz(t), 3); active columns = [0, 256*(v+1))
        const int v = ((t & 7) == 0) ? 3 : ((t & 3) == 0) ? 2 : ((t & 1) == 0) ? 1 : 0;
        const int nact = (v + 1) << 8;
        const float* hb_old = &g_hb[(t - 1) & 1][0][0][0];
        float*       hb_new = &g_hb[t & 1][0][0][0];
        const int CT = (v < 2) ? 4 : 8;
        const int ntask = nact / CT;     // 64 / 128 / 96 / 128

        for (int d = 0; d < DD; ++d) {
            const float* A1 = (d == 0) ? &g_xT[t - 1][0][0]
                                       : (hb_new + (d - 1) * HH * BB);
            const float* Wx = (d == 0) ? Wx0 : (Wxd + (d - 1) * HH * HH);

            if (blockIdx.x < ntask) {
                if (CT == 4)
                    do_stage<4>(t, d, Wx, Wh + d * HH * HH, bias + d * HH, out,
                                hb_old + d * HH * BB, A1, hb_new + d * HH * BB, red);
                else
                    do_stage<8>(t, d, Wx, Wh + d * HH * HH, bias + d * HH, out,
                                hb_old + d * HH * BB, A1, hb_new + d * HH * BB, red);
            } else {
                // Inactive columns: carry h(t-1) into hb_new and write out
                const int ninact = HH - nact;
                if (ninact > 0) {
                    const int ncb = NBLK - ntask;
                    const int total = ninact * BB;
                    const float* src = hb_old + d * HH * BB;
                    float*       dst = hb_new + d * HH * BB;
                    for (int i = (blockIdx.x - ntask) * NTHR + tid; i < total;
                         i += ncb * NTHR) {
                        const int m   = i / ninact;
                        const int col = nact + (i - m * ninact);
                        const float h = src[col * BB + m];
                        dst[col * BB + m] = h;
                        out[((m * TT + (t - 1)) * DD + d) * HH + col] = h;
                    }
                }
            }
            gridbar();
        }
    }
}

// ---------------------------------------------------------------------------
// x: [B][T][DIN] -> g_xT[t][k][m]  (lane-coalesced reads over k)
// ---------------------------------------------------------------------------
__global__ void xT_kernel(const float* __restrict__ x) {
    int idx = blockIdx.x * blockDim.x + threadIdx.x;
    if (idx >= TT * HH) return;
    int t = idx / HH;
    int k = idx - t * HH;
#pragma unroll
    for (int m = 0; m < BB; ++m)
        g_xT[t][k][m] = x[(m * TT + t) * HH + k];
}

// ---------------------------------------------------------------------------
// kernel_launch: graph-capturable, allocation-free
// inputs: x, Wx0, Wxd, Wh, b, periods (periods structure is fixed: 2^g blocks)
// ---------------------------------------------------------------------------
extern "C" void kernel_launch(void* const* d_in, const int* in_sizes, int n_in,
                              void* d_out, int out_size) {
    const float* x   = (const float*)d_in[0];
    const float* Wx0 = (const float*)d_in[1];
    const float* Wxd = (const float*)d_in[2];
    const float* Wh  = (const float*)d_in[3];
    const float* b   = (const float*)d_in[4];
    float* out = (float*)d_out;

    xT_kernel<<<(TT * HH + 255) / 256, 256>>>(x);
    cwrnn_kernel<<<NBLK, NTHR>>>(Wx0, Wxd, Wh, b, out);
}

// round 7
// speedup vs baseline: 2.8021x; 2.8021x over previous
#include <cuda_runtime.h>

#define BB   32      // batch (M)
#define TT   512     // time steps
#define HH   1024    // hidden / input dim
#define DD   4       // depth
#define NBLK 148     // persistent blocks (1 per SM, co-resident)
#define NTHR 512     // 16 warps
#define NW   16
#define CT   8       // GEMM tile columns
#define CC   64      // copy tile columns
#define NDIAG (TT + DD - 1)   // 515 wavefront diagonals

// Scratch (device globals: allocation is forbidden)
__device__ float g_h[3][DD][HH][BB];   // triple-buffered hidden state [diag%3][d][k][m]
__device__ float g_xT[TT][HH][BB];     // transposed input [t][k][m]
__device__ unsigned int g_slot[NBLK];  // per-block monotonic barrier slots (replay-safe)

// ---------------------------------------------------------------------------
// Atomic-free grid barrier: each block owns one slot (single writer).
// 148 threads poll one slot each in parallel. Slots grow monotonically across
// graph replays; `target` is base (value at launch entry) + local round.
// ---------------------------------------------------------------------------
__device__ __forceinline__ void gridbar(unsigned int target) {
    __syncthreads();
    if (threadIdx.x == 0) {
        __threadfence();  // publish this block's global writes
        asm volatile("st.global.release.gpu.u32 [%0], %1;"
                     :: "l"(&g_slot[blockIdx.x]), "r"(target) : "memory");
    }
    if (threadIdx.x < NBLK) {
        unsigned int v;
        do {
            asm volatile("ld.acquire.gpu.u32 %0, [%1];"
                         : "=r"(v) : "l"(&g_slot[threadIdx.x]) : "memory");
        } while (v < target);
    }
    __syncthreads();
}

__device__ __forceinline__ int nact_of(int t) {
    int v = ((t & 7) == 0) ? 3 : ((t & 3) == 0) ? 2 : ((t & 1) == 0) ? 1 : 0;
    return (v + 1) << 8;
}

// ---------------------------------------------------------------------------
// acc[c] += sum_{k in [k0,k0+kn)} A[k][lane] * W[k][c],  c = 0..7
// A is [K][32] lane-coalesced; W row-major [K][HH], pre-offset by col0.
// W loads are warp-uniform (broadcast); kn is always a multiple of 4.
// ---------------------------------------------------------------------------
__device__ __forceinline__ void dot8(const float* __restrict__ A,
                                     const float* __restrict__ W,
                                     int k0, int kn, int lane, float acc[CT]) {
    const float*  Ap = A + k0 * BB + lane;
    const float4* Wp = (const float4*)(W + (size_t)k0 * HH);
#pragma unroll 4
    for (int k = 0; k < kn; ++k) {
        float  a  = __ldg(Ap);
        float4 w0 = __ldg(Wp);
        float4 w1 = __ldg(Wp + 1);
        acc[0] += a * w0.x; acc[1] += a * w0.y;
        acc[2] += a * w0.z; acc[3] += a * w0.w;
        acc[4] += a * w1.x; acc[5] += a * w1.y;
        acc[6] += a * w1.z; acc[7] += a * w1.w;
        Ap += BB; Wp += HH / 4;
    }
}

// ---------------------------------------------------------------------------
// One 8-column GEMM tile of stage (t,d):
//   pre = A1 @ Wx[:,cols] + h_d(t-1) @ Wh_d[256g:, cols] + b ; h = tanh(pre)
// 16 warps k-split, SMEM cross-warp reduction, epilogue writes h + out.
// ---------------------------------------------------------------------------
__device__ __forceinline__ void gemm_tile(int t, int d, int col0, int bufR, int bufW,
                                          const float* __restrict__ Wx0,
                                          const float* __restrict__ Wxd,
                                          const float* __restrict__ Wh,
                                          const float* __restrict__ bias,
                                          float* __restrict__ out,
                                          float (*red)[NW * CT * BB / NW], int tid) {
    const int lane = tid & 31;
    const int wid  = tid >> 5;
    const int grp  = col0 >> 8;

    const float* A1 = (d == 0) ? &g_xT[t - 1][0][0] : &g_h[bufR][d - 1][0][0];
    const float* hR = &g_h[bufR][d][0][0];
    const float* Wx = ((d == 0) ? Wx0 : Wxd + (size_t)(d - 1) * HH * HH) + col0;
    const float* Wr = Wh + (size_t)d * HH * HH + col0;

    float acc[CT];
#pragma unroll
    for (int c = 0; c < CT; ++c) acc[c] = 0.f;

    // feed-forward: full K=1024, 64 rows per warp
    dot8(A1, Wx, wid * 64, 64, lane, acc);

    // recurrent: masked rows [256*grp, 1024), split 16 ways (64/48/32/16 each)
    const int base = grp << 8;
    const int rs   = (HH - base) >> 4;
    dot8(hR, Wr, base + wid * rs, rs, lane, acc);

    // cross-warp reduction: red[w][m*8 + c]
#pragma unroll
    for (int c = 0; c < CT; ++c) red[wid][lane * CT + c] = acc[c];
    __syncthreads();

    if (tid < CT * BB) {
        const int c = tid & 7;
        const int m = tid >> 3;
        float s = 0.f;
#pragma unroll
        for (int w = 0; w < NW; ++w) s += red[w][tid];
        const int   col = col0 + c;
        const float h   = tanhf(s + __ldg(bias + d * HH + col));
        g_h[bufW][d][col][m] = h;
        out[(((size_t)m * TT + (t - 1)) * DD + d) * HH + col] = h;  // coalesced over c
    }
    __syncthreads();
}

// Inactive columns of stage (t,d): carry h(t-1) forward, write out.
__device__ __forceinline__ void copy_tile(int t, int d, int col0, int bufR, int bufW,
                                          float* __restrict__ out, int tid) {
    const float* src = &g_h[bufR][d][0][0];
    float*       dst = &g_h[bufW][d][0][0];
#pragma unroll
    for (int i = tid; i < CC * BB; i += NTHR) {
        const int m = i >> 6;
        const int c = col0 + (i & (CC - 1));
        const float h = src[c * BB + m];
        dst[c * BB + m] = h;
        out[(((size_t)m * TT + (t - 1)) * DD + d) * HH + c] = h;
    }
}

// ---------------------------------------------------------------------------
// Persistent wavefront kernel: diagonal s = t + d, stages on a diagonal are
// independent. One grid barrier per diagonal (515) + 1 init barrier.
// ---------------------------------------------------------------------------
__global__ void __launch_bounds__(NTHR, 1)
cwrnn_kernel(const float* __restrict__ Wx0, const float* __restrict__ Wxd,
             const float* __restrict__ Wh, const float* __restrict__ bias,
             float* __restrict__ out) {
    __shared__ float red[NW][CT * BB];
    const int tid = threadIdx.x;
    const int bid = blockIdx.x;

    // per-launch barrier base (slots are monotonic across graph replays;
    // nothing has been written this launch yet, so this read is race-free)
    const unsigned int barbase = g_slot[bid];
    unsigned int r = 1;

    // zero all three h buffers (fresh state each launch / replay)
    {
        float* hz = &g_h[0][0][0][0];
        for (int i = bid * NTHR + tid; i < 3 * DD * HH * BB; i += NBLK * NTHR)
            hz[i] = 0.f;
    }
    gridbar(barbase + r); ++r;

    for (int s = 1; s <= NDIAG; ++s) {
        const int bufR = (s + 2) % 3;
        const int bufW = s % 3;

        // per-stage tile counts (stage d valid iff 1 <= t = s-d <= TT)
        int gcnt[DD], ccnt[DD];
        int gtot = 0, ctot = 0;
#pragma unroll
        for (int d = 0; d < DD; ++d) {
            const int t = s - d;
            int gc = 0, cc = 0;
            if (t >= 1 && t <= TT) {
                const int na = nact_of(t);
                gc = na >> 3;            // GEMM tiles of 8 cols
                cc = (HH - na) >> 6;     // copy tiles of 64 cols
            }
            gcnt[d] = gc; ccnt[d] = cc;
            gtot += gc; ctot += cc;
        }
        const int total = gtot + ctot;

        for (int idx = bid; idx < total; idx += NBLK) {
            if (idx < gtot) {
                int j = idx, d = 0;
                if (j >= gcnt[0]) { j -= gcnt[0]; d = 1;
                    if (j >= gcnt[1]) { j -= gcnt[1]; d = 2;
                        if (j >= gcnt[2]) { j -= gcnt[2]; d = 3; } } }
                gemm_tile(s - d, d, j * CT, bufR, bufW, Wx0, Wxd, Wh, bias, out, red, tid);
            } else {
                int j = idx - gtot, d = 0;
                if (j >= ccnt[0]) { j -= ccnt[0]; d = 1;
                    if (j >= ccnt[1]) { j -= ccnt[1]; d = 2;
                        if (j >= ccnt[2]) { j -= ccnt[2]; d = 3; } } }
                copy_tile(s - d, d, nact_of(s - d) + j * CC, bufR, bufW, out, tid);
            }
        }
        gridbar(barbase + r); ++r;
    }
}

// ---------------------------------------------------------------------------
// x: [B][T][DIN] -> g_xT[t][k][m]
// ---------------------------------------------------------------------------
__global__ void xT_kernel(const float* __restrict__ x) {
    int idx = blockIdx.x * blockDim.x + threadIdx.x;
    if (idx >= TT * HH) return;
    int t = idx / HH;
    int k = idx - t * HH;
#pragma unroll
    for (int m = 0; m < BB; ++m)
        g_xT[t][k][m] = x[((size_t)m * TT + t) * HH + k];
}

// ---------------------------------------------------------------------------
// kernel_launch: graph-capturable, allocation-free
// inputs: x, Wx0, Wxd, Wh, b, periods (period structure is compile-time fixed)
// ---------------------------------------------------------------------------
extern "C" void kernel_launch(void* const* d_in, const int* in_sizes, int n_in,
                              void* d_out, int out_size) {
    const float* x   = (const float*)d_in[0];
    const float* Wx0 = (const float*)d_in[1];
    const float* Wxd = (const float*)d_in[2];
    const float* Wh  = (const float*)d_in[3];
    const float* b   = (const float*)d_in[4];
    float* out = (float*)d_out;

    xT_kernel<<<(TT * HH + 255) / 256, 256>>>(x);
    cwrnn_kernel<<<NBLK, NTHR>>>(Wx0, Wxd, Wh, b, out);
}

// round 8
// speedup vs baseline: 3.0959x; 1.1048x over previous
#include <cuda_runtime.h>

#define BB    32
#define TT    512
#define HH    1024
#define DD    4
#define NBLK  148
#define NTHR  512
#define NG    2                 // task groups per block
#define GW    8                 // warps per group
#define GT    256               // threads per group
#define NSLOT (NBLK * NG)       // 296 task slots; max tasks/diagonal = 292
#define NDIAG (TT + DD - 1)

// Device-global scratch (allocation forbidden)
// Activations packed [k/4][m][4] so A-operand loads are float4.
__device__ float g_h[2][DD][HH / 4][BB][4];   // double-buffered hidden state
__device__ float g_xT[TT][HH / 4][BB][4];     // packed transposed input
__device__ unsigned int g_slot[NBLK];         // monotonic barrier slots (replay-safe)

// ---------------------------------------------------------------------------
// Atomic-free grid barrier (one writer per slot; 148 parallel pollers)
// ---------------------------------------------------------------------------
__device__ __forceinline__ void gridbar(unsigned int target) {
    __syncthreads();
    if (threadIdx.x == 0) {
        __threadfence();
        asm volatile("st.global.release.gpu.u32 [%0], %1;"
                     :: "l"(&g_slot[blockIdx.x]), "r"(target) : "memory");
    }
    if (threadIdx.x < NBLK) {
        unsigned int v;
        do {
            asm volatile("ld.acquire.gpu.u32 %0, [%1];"
                         : "=r"(v) : "l"(&g_slot[threadIdx.x]) : "memory");
        } while (v < target);
    }
    __syncthreads();
}

__device__ __forceinline__ void barWG(int grp) {
    asm volatile("bar.sync %0, %1;" :: "r"(grp + 1), "r"(GT) : "memory");
}

__device__ __forceinline__ int nact_of(int t) {
    int v = ((t & 7) == 0) ? 3 : ((t & 3) == 0) ? 2 : ((t & 1) == 0) ? 1 : 0;
    return (v + 1) << 8;
}

#define FMA8A(av, wlo, whi)                                                   \
    acc[0] += (av) * (wlo).x; acc[1] += (av) * (wlo).y;                       \
    acc[2] += (av) * (wlo).z; acc[3] += (av) * (wlo).w;                       \
    acc[4] += (av) * (whi).x; acc[5] += (av) * (whi).y;                       \
    acc[6] += (av) * (whi).z; acc[7] += (av) * (whi).w;

// ---------------------------------------------------------------------------
// acc[c] += sum_{k in [k0,k0+kn)} A[k][lane] * W[k][col0+c], c=0..7
// A packed [k/4][32][4] (float4 per lane per 4k); W row-major, col0-offset.
// kn is a multiple of 4. A read L2-coherent (cross-SM producer).
// ---------------------------------------------------------------------------
__device__ __forceinline__ void dotseg(const float* __restrict__ Apack,
                                       const float* __restrict__ W,
                                       int k0, int kn, int lane, float acc[8]) {
    const float4* Ap = (const float4*)(Apack + (k0 >> 2) * (BB * 4) + lane * 4);
    const float4* Wp = (const float4*)(W + (size_t)k0 * HH);
#pragma unroll 2
    for (int kk = 0; kk < kn; kk += 4) {
        float4 a = __ldcg(Ap); Ap += BB;
        float4 w0, w1;
        w0 = __ldg(Wp + 0);   w1 = __ldg(Wp + 1);   FMA8A(a.x, w0, w1);
        w0 = __ldg(Wp + 256); w1 = __ldg(Wp + 257); FMA8A(a.y, w0, w1);
        w0 = __ldg(Wp + 512); w1 = __ldg(Wp + 513); FMA8A(a.z, w0, w1);
        w0 = __ldg(Wp + 768); w1 = __ldg(Wp + 769); FMA8A(a.w, w0, w1);
        Wp += 1024;
    }
}

// ---------------------------------------------------------------------------
// One 8-column GEMM tile of stage (t,d), executed by an 8-warp group.
// ---------------------------------------------------------------------------
__device__ __forceinline__ void gemm_tile(int t, int d, int col0, int bufR, int bufW,
                                          const float* __restrict__ Wx0,
                                          const float* __restrict__ Wxd,
                                          const float* __restrict__ Wh,
                                          const float* __restrict__ bias,
                                          float* __restrict__ out,
                                          float (*red)[GT], int tg, int grp) {
    const int lane = tg & 31;
    const int wid  = tg >> 5;          // 0..7
    const int g    = col0 >> 8;

    const float* A1 = (d == 0) ? &g_xT[t - 1][0][0][0] : &g_h[bufR][d - 1][0][0][0];
    const float* hR = &g_h[bufR][d][0][0][0];
    const float* Wx = ((d == 0) ? Wx0 : Wxd + (size_t)(d - 1) * HH * HH) + col0;
    const float* Wr = Wh + (size_t)d * HH * HH + col0;

    float acc[8];
#pragma unroll
    for (int c = 0; c < 8; ++c) acc[c] = 0.f;

    // feed-forward: K=1024 split 8 ways
    dotseg(A1, Wx, wid * 128, 128, lane, acc);
    // recurrent: rows [256g, 1024) split 8 ways (128/96/64/32 per warp)
    const int base = g << 8;
    const int rs   = (HH - base) >> 3;
    dotseg(hR, Wr, base + wid * rs, rs, lane, acc);

#pragma unroll
    for (int c = 0; c < 8; ++c) red[wid][lane * 8 + c] = acc[c];
    barWG(grp);

    {   // 256 threads, 256 outputs: one each
        const int c = tg & 7, m = tg >> 3;
        float s = 0.f;
#pragma unroll
        for (int w = 0; w < GW; ++w) s += red[w][tg];
        const int   col = col0 + c;
        const float h   = tanhf(s + __ldg(bias + d * HH + col));
        g_h[bufW][d][col >> 2][m][col & 3] = h;
        out[(((size_t)m * TT + (t - 1)) * DD + d) * HH + col] = h;
    }
    barWG(grp);   // protect red[] reuse by next task
}

// Inactive 64-column tile: carry h(t-1), write out (all float4).
__device__ __forceinline__ void copy_tile(int t, int d, int col0, int bufR, int bufW,
                                          float* __restrict__ out, int tg) {
    const float4* src = (const float4*)&g_h[bufR][d][col0 >> 2][0][0];
    float4*       dst = (float4*)&g_h[bufW][d][col0 >> 2][0][0];
#pragma unroll
    for (int i = tg; i < 16 * BB; i += GT) {
        const int c4 = i >> 5, m = i & 31;
        float4 v = __ldcg(src + c4 * BB + m);
        dst[c4 * BB + m] = v;
        *(float4*)(out + (((size_t)m * TT + (t - 1)) * DD + d) * HH + col0 + c4 * 4) = v;
    }
}

// Decode task index (g-major cost-descending GEMM tiles, then copy tiles).
// Returns: typ (0=gemm,1=copy,-1=none), d, col0.
__device__ __forceinline__ void decode_task(int task, const int act[DD],
                                            int ng, int& typ, int& dd, int& col0) {
    typ = -1;
    int rem = task;
    if (rem < ng) {
#pragma unroll
        for (int g = 0; g < 4; ++g)
#pragma unroll
            for (int d = 0; d < DD; ++d)
                if (act[d] >= ((g + 1) << 8)) {
                    if (typ < 0 && rem < 32) { typ = 0; dd = d; col0 = (g << 8) + rem * 8; }
                    if (typ < 0) rem -= 32;
                }
    } else {
        rem -= ng;
#pragma unroll
        for (int d = 0; d < DD; ++d)
            if (act[d] > 0) {
                const int nc = (HH - act[d]) >> 6;
                if (typ < 0 && rem < nc) { typ = 1; dd = d; col0 = act[d] + rem * 64; }
                if (typ < 0) rem -= nc;
            }
    }
}

// ---------------------------------------------------------------------------
// Persistent wavefront kernel: one task-wave + one grid barrier per diagonal.
// ---------------------------------------------------------------------------
__global__ void __launch_bounds__(NTHR, 1)
cwrnn_kernel(const float* __restrict__ Wx0, const float* __restrict__ Wxd,
             const float* __restrict__ Wh, const float* __restrict__ bias,
             float* __restrict__ out) {
    __shared__ float red[NG][GW][GT];
    const int tid = threadIdx.x;
    const int bid = blockIdx.x;
    const int grp = tid >> 8;      // 0/1
    const int tg  = tid & 255;

    const unsigned int barbase = g_slot[bid];
    unsigned int r = 1;

    {   // zero both h buffers (fresh state every launch / graph replay)
        float* hz = &g_h[0][0][0][0][0];
        for (int i = bid * NTHR + tid; i < 2 * DD * HH * BB; i += NBLK * NTHR)
            hz[i] = 0.f;
    }
    gridbar(barbase + r); ++r;

    for (int s = 1; s <= NDIAG; ++s) {
        const int bufR = (s - 1) & 1;
        const int bufW = s & 1;

        int act[DD];
        int ng = 0, ncopy = 0;
#pragma unroll
        for (int d = 0; d < DD; ++d) {
            const int t = s - d;
            act[d] = (t >= 1 && t <= TT) ? nact_of(t) : 0;
            ng += act[d] >> 3;
            if (act[d]) ncopy += (HH - act[d]) >> 6;
        }
        const int ntask = ng + ncopy;

        // snake assignment: block b handles tasks {b, NSLOT-1-b} (single wave)
        const int slot0 = (grp == 0) ? bid : (NSLOT - 1 - bid);
        for (int task = slot0; task < ntask; task += NSLOT) {
            int typ, dd, col0;
            decode_task(task, act, ng, typ, dd, col0);
            if (typ == 0)
                gemm_tile(s - dd, dd, col0, bufR, bufW, Wx0, Wxd, Wh, bias, out,
                          red[grp], tg, grp);
            else if (typ == 1)
                copy_tile(s - dd, dd, col0, bufR, bufW, out, tg);
        }
        gridbar(barbase + r); ++r;
    }
}

// ---------------------------------------------------------------------------
// x [B][T][DIN] -> packed g_xT[t][k/4][m][4]  (float4 loads and stores)
// ---------------------------------------------------------------------------
__global__ void xT_kernel(const float* __restrict__ x) {
    int idx = blockIdx.x * blockDim.x + threadIdx.x;   // t * k4 * m
    if (idx >= TT * (HH / 4) * BB) return;
    const int k4 = idx & 255;
    const int m  = (idx >> 8) & 31;
    const int t  = idx >> 13;
    float4 v = *(const float4*)(x + ((size_t)m * TT + t) * HH + k4 * 4);
    *(float4*)(&g_xT[t][k4][m][0]) = v;
}

// ---------------------------------------------------------------------------
// kernel_launch: graph-capturable, allocation-free
// ---------------------------------------------------------------------------
extern "C" void kernel_launch(void* const* d_in, const int* in_sizes, int n_in,
                              void* d_out, int out_size) {
    const float* x   = (const float*)d_in[0];
    const float* Wx0 = (const float*)d_in[1];
    const float* Wxd = (const float*)d_in[2];
    const float* Wh  = (const float*)d_in[3];
    const float* b   = (const float*)d_in[4];
    float* out = (float*)d_out;

    xT_kernel<<<(TT * (HH / 4) * BB + 255) / 256, 256>>>(x);
    cwrnn_kernel<<<NBLK, NTHR>>>(Wx0, Wxd, Wh, b, out);
}

// round 9
// speedup vs baseline: 3.4378x; 1.1105x over previous
#include <cuda_runtime.h>

#define BB    32
#define TT    512
#define HH    1024
#define DD    4
#define NBLK  148
#define NTHR  512
#define GW    8                 // warps per slot (group)
#define GT    256               // threads per slot
#define NSLOT 296               // 2 slots per block
#define NDIAG (TT + DD - 1)     // 515

// Device-global scratch (allocation forbidden)
__device__ float g_h[2][DD][HH / 4][BB][4];   // double-buffered hidden, packed [k/4][m][4]
__device__ float g_xT[TT][HH / 4][BB][4];     // packed transposed input
__device__ unsigned int g_slot[NBLK];         // monotonic barrier slots (replay-safe)

// ---------------------------------------------------------------------------
// Atomic-free grid barrier (one writer per slot; 148 parallel pollers)
// ---------------------------------------------------------------------------
__device__ __forceinline__ void gridbar(unsigned int target) {
    __syncthreads();
    if (threadIdx.x == 0) {
        __threadfence();
        asm volatile("st.global.release.gpu.u32 [%0], %1;"
                     :: "l"(&g_slot[blockIdx.x]), "r"(target) : "memory");
    }
    if (threadIdx.x < NBLK) {
        unsigned int v;
        do {
            asm volatile("ld.acquire.gpu.u32 %0, [%1];"
                         : "=r"(v) : "l"(&g_slot[threadIdx.x]) : "memory");
        } while (v < target);
    }
    __syncthreads();
}

__device__ __forceinline__ void barWG(int grp) {
    asm volatile("bar.sync %0, %1;" :: "r"(grp + 1), "r"(GT) : "memory");
}

__device__ __forceinline__ int nact_of(int t) {
    int v = ((t & 7) == 0) ? 3 : ((t & 3) == 0) ? 2 : ((t & 1) == 0) ? 1 : 0;
    return (v + 1) << 8;
}

#define FMA8A(av, wlo, whi)                                                   \
    acc[0] += (av) * (wlo).x; acc[1] += (av) * (wlo).y;                       \
    acc[2] += (av) * (wlo).z; acc[3] += (av) * (wlo).w;                       \
    acc[4] += (av) * (whi).x; acc[5] += (av) * (whi).y;                       \
    acc[6] += (av) * (whi).z; acc[7] += (av) * (whi).w;

// ---------------------------------------------------------------------------
// acc[c] += sum_{k in [k0,k0+kn)} A[k][lane] * W[k][col0+c], c=0..7
// A packed [k/4][32][4], read .cg (L2 only, keeps L1 free for W).
// W row-major [K][HH], col0-offset, read .ca (L1-resident: static ownership).
// ---------------------------------------------------------------------------
__device__ __forceinline__ void dotseg(const float* __restrict__ Apack,
                                       const float* __restrict__ W,
                                       int k0, int kn, int lane, float acc[8]) {
    const float4* Ap = (const float4*)(Apack + (k0 >> 2) * (BB * 4) + lane * 4);
    const float4* Wp = (const float4*)(W + (size_t)k0 * HH);
#pragma unroll 2
    for (int kk = 0; kk < kn; kk += 4) {
        float4 a = __ldcg(Ap); Ap += BB;
        float4 w0, w1;
        w0 = __ldg(Wp + 0);   w1 = __ldg(Wp + 1);   FMA8A(a.x, w0, w1);
        w0 = __ldg(Wp + 256); w1 = __ldg(Wp + 257); FMA8A(a.y, w0, w1);
        w0 = __ldg(Wp + 512); w1 = __ldg(Wp + 513); FMA8A(a.z, w0, w1);
        w0 = __ldg(Wp + 768); w1 = __ldg(Wp + 769); FMA8A(a.w, w0, w1);
        Wp += 1024;
    }
}

// ---------------------------------------------------------------------------
// One 8-column GEMM tile of stage (t,d), executed by an 8-warp slot.
// ---------------------------------------------------------------------------
__device__ __forceinline__ void gemm_tile(int t, int d, int col0, int bufR, int bufW,
                                          const float* __restrict__ Wx0,
                                          const float* __restrict__ Wxd,
                                          const float* __restrict__ Wh,
                                          const float* __restrict__ bias,
                                          float* __restrict__ out,
                                          float (*red)[GT], int tg, int grp) {
    const int lane = tg & 31;
    const int wid  = tg >> 5;
    const int g    = col0 >> 8;

    const float* A1 = (d == 0) ? &g_xT[t - 1][0][0][0] : &g_h[bufR][d - 1][0][0][0];
    const float* hR = &g_h[bufR][d][0][0][0];
    const float* Wx = ((d == 0) ? Wx0 : Wxd + (size_t)(d - 1) * HH * HH) + col0;
    const float* Wr = Wh + (size_t)d * HH * HH + col0;

    float acc[8];
#pragma unroll
    for (int c = 0; c < 8; ++c) acc[c] = 0.f;

    dotseg(A1, Wx, wid * 128, 128, lane, acc);            // FF: K=1024 / 8 warps
    const int base = g << 8;                              // rec rows [256g, 1024)
    const int rs   = (HH - base) >> 3;
    dotseg(hR, Wr, base + wid * rs, rs, lane, acc);

#pragma unroll
    for (int c = 0; c < 8; ++c) red[wid][lane * 8 + c] = acc[c];
    barWG(grp);

    {
        const int c = tg & 7, m = tg >> 3;
        float s = 0.f;
#pragma unroll
        for (int w = 0; w < GW; ++w) s += red[w][tg];
        const int   col = col0 + c;
        const float h   = tanhf(s + __ldg(bias + d * HH + col));
        g_h[bufW][d][col >> 2][m][col & 3] = h;
        out[(((size_t)m * TT + (t - 1)) * DD + d) * HH + col] = h;
    }
    barWG(grp);
}

// Inactive 64-column tile: carry h(t-1), write out.
__device__ __forceinline__ void copy_tile(int t, int d, int col0, int bufR, int bufW,
                                          float* __restrict__ out, int tg) {
    const float4* src = (const float4*)&g_h[bufR][d][col0 >> 2][0][0];
    float4*       dst = (float4*)&g_h[bufW][d][col0 >> 2][0][0];
#pragma unroll
    for (int i = tg; i < 16 * BB; i += GT) {
        const int c4 = i >> 5, m = i & 31;
        float4 v = __ldcg(src + c4 * BB + m);
        dst[c4 * BB + m] = v;
        *(float4*)(out + (((size_t)m * TT + (t - 1)) * DD + d) * HH + col0 + c4 * 4) = v;
    }
}

// ---------------------------------------------------------------------------
// Static slot->task map. Group-g tile active on diagonal s iff d ≡ s (mod 2^g)
// (then t = s-d has nact covering group g). Exactly <=1 task per slot.
//   slots 0..127   : g0 tile (d = slot/32, j = slot%32), active when t valid
//   slots 128..191 : g1 parity pair (depths {0,1} or {2,3}), d = base+(s&1)
//   slots 192..223 : g2 4-depth bundle, d = s&3
//   slots 224..255 : g3 4-depth bundle, d = s&7 (if <4)
//   slots 256..295 : copy tasks (<=36 per diagonal)
// ---------------------------------------------------------------------------
__device__ __forceinline__ void slot_task(int slot, int s,
                                          int& typ, int& dd, int& col0) {
    typ = -1;
    if (slot < 128) {
        const int d = slot >> 5;
        const int t = s - d;
        if (t >= 1 && t <= TT) { typ = 0; dd = d; col0 = (slot & 31) << 3; }
    } else if (slot < 192) {
        const int q = slot - 128;
        const int d = ((q >> 5) << 1) + (s & 1);
        const int t = s - d;
        if (t >= 1 && t <= TT) { typ = 0; dd = d; col0 = 256 + ((q & 31) << 3); }
    } else if (slot < 224) {
        const int d = s & 3;
        const int t = s - d;
        if (t >= 1 && t <= TT) { typ = 0; dd = d; col0 = 512 + ((slot - 192) << 3); }
    } else if (slot < 256) {
        const int d = s & 7;
        if (d < 4) {
            const int t = s - d;
            if (t >= 1 && t <= TT) { typ = 0; dd = d; col0 = 768 + ((slot - 224) << 3); }
        }
    } else {
        int rem = slot - 256;
#pragma unroll
        for (int d = 0; d < DD; ++d) {
            const int t = s - d;
            if (t >= 1 && t <= TT) {
                const int na = nact_of(t);
                const int nc = (HH - na) >> 6;
                if (typ < 0 && rem < nc) { typ = 1; dd = d; col0 = na + (rem << 6); }
                if (typ < 0) rem -= nc;
            }
        }
    }
}

// ---------------------------------------------------------------------------
// Persistent wavefront kernel: 1 task per slot per diagonal, 1 barrier each.
// Static W ownership keeps each SM's weight tiles L1-resident for the launch.
// ---------------------------------------------------------------------------
__global__ void __launch_bounds__(NTHR, 1)
cwrnn_kernel(const float* __restrict__ Wx0, const float* __restrict__ Wxd,
             const float* __restrict__ Wh, const float* __restrict__ bias,
             float* __restrict__ out) {
    __shared__ float red[2][GW][GT];
    const int tid = threadIdx.x;
    const int bid = blockIdx.x;
    const int grp = tid >> 8;
    const int tg  = tid & 255;
    const int slot = (grp == 0) ? bid : (NSLOT - 1 - bid);   // snake pairing

    const unsigned int barbase = g_slot[bid];
    unsigned int r = 1;

    {   // zero both h buffers (fresh state each launch / replay)
        float* hz = &g_h[0][0][0][0][0];
        for (int i = bid * NTHR + tid; i < 2 * DD * HH * BB; i += NBLK * NTHR)
            hz[i] = 0.f;
    }
    gridbar(barbase + r); ++r;

    for (int s = 1; s <= NDIAG; ++s) {
        const int bufR = (s - 1) & 1;
        const int bufW = s & 1;

        int typ, dd, col0;
        slot_task(slot, s, typ, dd, col0);
        if (typ == 0)
            gemm_tile(s - dd, dd, col0, bufR, bufW, Wx0, Wxd, Wh, bias, out,
                      red[grp], tg, grp);
        else if (typ == 1)
            copy_tile(s - dd, dd, col0, bufR, bufW, out, tg);

        gridbar(barbase + r); ++r;
    }
}

// ---------------------------------------------------------------------------
// x [B][T][DIN] -> packed g_xT[t][k/4][m][4]
// ---------------------------------------------------------------------------
__global__ void xT_kernel(const float* __restrict__ x) {
    int idx = blockIdx.x * blockDim.x + threadIdx.x;
    if (idx >= TT * (HH / 4) * BB) return;
    const int k4 = idx & 255;
    const int m  = (idx >> 8) & 31;
    const int t  = idx >> 13;
    float4 v = *(const float4*)(x + ((size_t)m * TT + t) * HH + k4 * 4);
    *(float4*)(&g_xT[t][k4][m][0]) = v;
}

// ---------------------------------------------------------------------------
// kernel_launch: graph-capturable, allocation-free
// ---------------------------------------------------------------------------
extern "C" void kernel_launch(void* const* d_in, const int* in_sizes, int n_in,
                              void* d_out, int out_size) {
    const float* x   = (const float*)d_in[0];
    const float* Wx0 = (const float*)d_in[1];
    const float* Wxd = (const float*)d_in[2];
    const float* Wh  = (const float*)d_in[3];
    const float* b   = (const float*)d_in[4];
    float* out = (float*)d_out;

    xT_kernel<<<(TT * (HH / 4) * BB + 255) / 256, 256>>>(x);
    cwrnn_kernel<<<NBLK, NTHR>>>(Wx0, Wxd, Wh, b, out);
}